// round 13
// baseline (speedup 1.0000x reference)
#include <cuda_runtime.h>
#include <cstdint>

#define E        300
#define E4       75
#define V        50000
#define RS       75      // uint2 (4 bf16) per row
#define SEQ      2048
#define BATCH    64
#define CPB      4
#define TOK_PER_CTA 512
#define TOK_PER_WARP 32
#define ATTN_H   150
#define NC       34
#define PSTRIDE  304
#define NWARP    16

typedef unsigned long long u64;
typedef unsigned int u32;

// Scratch (device globals; zero-init, no allocation)
__device__ __align__(16) uint2 g_embh[V * RS];   // 30 MB bf16 table
__device__ float g_sc1[V];                        // scaled stage-1 scores
__device__ __align__(16) float g_part[BATCH * CPB * PSTRIDE];
__device__ __align__(16) float g_h1[BATCH * E];
__device__ __align__(16) float g_r [BATCH * E];
__device__ int g_cnt[2][BATCH];                   // winner self-resets

__device__ __forceinline__ u64 pk2(float lo, float hi) {
    u64 r; asm("mov.b64 %0, {%1, %2};" : "=l"(r) : "f"(lo), "f"(hi)); return r;
}
__device__ __forceinline__ void upk2(u64 v, float& lo, float& hi) {
    asm("mov.b64 {%0, %1}, %2;" : "=f"(lo), "=f"(hi) : "l"(v));
}
__device__ __forceinline__ u64 fma2(u64 a, u64 b, u64 c) {
    u64 r; asm("fma.rn.f32x2 %0, %1, %2, %3;" : "=l"(r) : "l"(a), "l"(b), "l"(c));
    return r;
}
// pack float4 -> 4 bf16 (value order preserved: x,y | z,w)
__device__ __forceinline__ uint2 pkbf4(float4 v) {
    uint2 r;
    asm("cvt.rn.bf16x2.f32 %0, %1, %2;" : "=r"(r.x) : "f"(v.y), "f"(v.x));
    asm("cvt.rn.bf16x2.f32 %0, %1, %2;" : "=r"(r.y) : "f"(v.w), "f"(v.z));
    return r;
}
// u32 holding 2 bf16 -> packed f32x2 (bf16 is the top half of f32)
__device__ __forceinline__ u64 bfp(u32 u) {
    u32 lo = u << 16, hi = u & 0xFFFF0000u;
    u64 r; asm("mov.b64 %0, {%1, %2};" : "=l"(r) : "r"(lo), "r"(hi));
    return r;
}
__device__ __forceinline__ float dot4(float4 a, float4 b) {
    return a.x * b.x + a.y * b.y + a.z * b.z + a.w * b.w;
}

// ---------------------------------------------------------------------------
// Prep: stream fp32 table -> bf16 table + fused scores1[v] = emb[v]·q·scale.
// One warp per row, persistent, prefetch-1.
// ---------------------------------------------------------------------------
__global__ __launch_bounds__(512) void prep_kernel(
    const float* __restrict__ emb, const float* __restrict__ q_in)
{
    const int lane = threadIdx.x & 31;
    const int gw   = blockIdx.x * NWARP + (threadIdx.x >> 5);
    const int nw   = gridDim.x * NWARP;
    const float4 fz = make_float4(0.f, 0.f, 0.f, 0.f);
    const float4* __restrict__ emb4 = (const float4*)emb;
    const float4* __restrict__ qp4  = (const float4*)q_in;

    float4 qa = qp4[lane];
    float4 qb = qp4[lane + 32];
    float4 qc = (lane < 11) ? qp4[lane + 64] : fz;

    if (gw >= V) return;
    const float4* sp = emb4 + (long long)gw * E4;
    float4 na = sp[lane], nb = sp[lane + 32];
    float4 nc = (lane < 11) ? sp[lane + 64] : fz;

    for (int v = gw; v < V; v += nw) {
        float4 a = na, b = nb, c = nc;
        int vn = v + nw;
        if (vn < V) {
            const float4* np = emb4 + (long long)vn * E4;
            na = np[lane]; nb = np[lane + 32];
            if (lane < 11) nc = np[lane + 64];
        }
        float s = dot4(a, qa) + dot4(b, qb) + dot4(c, qc);
        #pragma unroll
        for (int o = 16; o; o >>= 1) s += __shfl_xor_sync(0xffffffffu, s, o);
        if (lane == 0) g_sc1[v] = s * 0.05773502691896258f;

        uint2* dst = g_embh + (long long)v * RS;
        dst[lane]      = pkbf4(a);
        dst[lane + 32] = pkbf4(b);
        if (lane < 11) dst[lane + 64] = pkbf4(c);
    }
}

// ---------------------------------------------------------------------------
// Fused stage kernel on the bf16 table. grid=(CPB,BATCH), 512 thr, 2 CTA/SM.
//   STAGE 1: weight = exp(g_sc1[token]) LOOKUP (no dot/shfl chain);
//            h1 -> g_h1;  r = Wat @ (h1 @ Wat) -> g_r   (last CTA per batch)
//   STAGE 2: dot with r[b] in FFMA2;  out = [h1,h2]@Wout + bias
// ---------------------------------------------------------------------------
template<int STAGE>
__global__ __launch_bounds__(512, 2) void fused_stage_kernel(
    const int* __restrict__ input_x,
    const float* __restrict__ Wat,
    const float* __restrict__ Wout,
    const float* __restrict__ bias,
    float* __restrict__ out)
{
    __shared__ float4 wacc[NWARP * 76];
    __shared__ float  ll[NWARP];
    __shared__ float  hs[E], h1s[E];
    __shared__ float  q2part[NWARP][152];
    __shared__ float  q2s[152];
    __shared__ float  opart[NWARP][NC];
    __shared__ int    isLast;

    const int slice = blockIdx.x;
    const int b     = blockIdx.y;
    const int tid   = threadIdx.x;
    const int w     = tid >> 5;
    const int lane  = tid & 31;
    uint2 uz2; uz2.x = 0u; uz2.y = 0u;
    const float4 fz = make_float4(0.f, 0.f, 0.f, 0.f);

    const int myidx = input_x[b * SEQ + slice * TOK_PER_CTA + w * TOK_PER_WARP + lane];

    u64 qa0 = 0, qa1 = 0, qb0 = 0, qb1 = 0, qc0 = 0, qc1 = 0;
    float wt_all = 0.f, l = 0.f;
    if (STAGE == 2) {
        const float4* qp4 = (const float4*)(g_r + b * E);
        float4 t0 = qp4[lane];
        float4 t1 = qp4[lane + 32];
        float4 t2 = (lane < 11) ? qp4[lane + 64] : fz;
        qa0 = pk2(t0.x, t0.y); qa1 = pk2(t0.z, t0.w);
        qb0 = pk2(t1.x, t1.y); qb1 = pk2(t1.z, t1.w);
        qc0 = pk2(t2.x, t2.y); qc1 = pk2(t2.z, t2.w);
    } else {
        wt_all = __expf(g_sc1[myidx]);
        l = wt_all;
        #pragma unroll
        for (int o = 16; o; o >>= 1) l += __shfl_xor_sync(0xffffffffu, l, o);
    }

    u64 Ax = 0, Ay = 0, Bx = 0, By = 0, Cx = 0, Cy = 0;

    int r0 = __shfl_sync(0xffffffffu, myidx, 0);
    const uint2* sp0 = g_embh + (long long)r0 * RS;
    uint2 na = sp0[lane], nb = sp0[lane + 32];
    uint2 nc = (lane < 11) ? sp0[lane + 64] : uz2;

    #pragma unroll 2
    for (int t = 0; t < TOK_PER_WARP; t++) {
        uint2 ca = na, cb = nb, cc = nc;
        if (t + 1 < TOK_PER_WARP) {
            int rn = __shfl_sync(0xffffffffu, myidx, t + 1);
            const uint2* np = g_embh + (long long)rn * RS;
            na = np[lane]; nb = np[lane + 32];
            if (lane < 11) nc = np[lane + 64];
        }

        u64 p0 = bfp(ca.x), p1 = bfp(ca.y);
        u64 p2 = bfp(cb.x), p3 = bfp(cb.y);
        u64 p4 = bfp(cc.x), p5 = bfp(cc.y);

        float wt;
        if (STAGE == 2) {
            u64 d = fma2(p0, qa0, 0ull);
            d = fma2(p1, qa1, d);
            d = fma2(p2, qb0, d);
            d = fma2(p3, qb1, d);
            d = fma2(p4, qc0, d);
            d = fma2(p5, qc1, d);
            float lo, hi; upk2(d, lo, hi);
            float s = lo + hi;
            #pragma unroll
            for (int o = 16; o; o >>= 1) s += __shfl_xor_sync(0xffffffffu, s, o);
            wt = __expf(s);
            l += wt;
        } else {
            wt = __shfl_sync(0xffffffffu, wt_all, t);
        }
        u64 ww = pk2(wt, wt);
        Ax = fma2(p0, ww, Ax);  Ay = fma2(p1, ww, Ay);
        Bx = fma2(p2, ww, Bx);  By = fma2(p3, ww, By);
        Cx = fma2(p4, ww, Cx);  Cy = fma2(p5, ww, Cy);
    }

    // ---- CTA merge of 16 warp partials (pure sums)
    if (lane == 0) ll[w] = l;
    ulonglong2* waccu = (ulonglong2*)wacc;
    { ulonglong2 v; v.x = Ax; v.y = Ay; waccu[w * 76 + lane]      = v; }
    { ulonglong2 v; v.x = Bx; v.y = By; waccu[w * 76 + lane + 32] = v; }
    if (lane < 11) { ulonglong2 v; v.x = Cx; v.y = Cy; waccu[w * 76 + lane + 64] = v; }
    __syncthreads();

    float* p = g_part + (b * CPB + slice) * PSTRIDE;
    if (tid < E4) {
        float4 ssum = fz;
        #pragma unroll
        for (int i = 0; i < NWARP; i++) {
            float4 v = wacc[i * 76 + tid];
            ssum.x += v.x; ssum.y += v.y; ssum.z += v.z; ssum.w += v.w;
        }
        ((float4*)p)[tid] = ssum;
    }
    if (tid == 0) {
        float Ls = 0.f;
        #pragma unroll
        for (int i = 0; i < NWARP; i++) Ls += ll[i];
        p[300] = Ls;
    }

    // ---- Last CTA per batch merges CPB partials + epilogue
    __syncthreads();
    if (tid == 0) {
        __threadfence();
        int old = atomicAdd(&g_cnt[STAGE - 1][b], 1);
        isLast = (old == CPB - 1);
        if (isLast) g_cnt[STAGE - 1][b] = 0;
    }
    __syncthreads();
    if (!isLast) return;
    __threadfence();

    const float* pb = g_part + b * CPB * PSTRIDE;
    if (tid == 0) {
        float Lg = 0.f;
        #pragma unroll
        for (int i = 0; i < CPB; i++) Lg += pb[i * PSTRIDE + 300];
        q2s[151] = 1.f / Lg;
    }
    __syncthreads();
    const float invL = q2s[151];

    if (tid < E) {
        float s = 0.f;
        #pragma unroll
        for (int i = 0; i < CPB; i++) s += pb[i * PSTRIDE + tid];
        s *= invL;
        hs[tid] = s;
        if (STAGE == 1) g_h1[b * E + tid] = s;
        else            h1s[tid] = g_h1[b * E + tid];
    }
    __syncthreads();

    if (STAGE == 1) {
        // q2 = h1 @ Wat
        float a5[5] = {0.f, 0.f, 0.f, 0.f, 0.f};
        for (int e = w; e < E; e += NWARP) {
            float hv = hs[e];
            const float* wr = Wat + e * ATTN_H;
            #pragma unroll
            for (int c = 0; c < 5; c++) {
                int h = lane + 32 * c;
                if (h < ATTN_H) a5[c] += hv * wr[h];
            }
        }
        #pragma unroll
        for (int c = 0; c < 5; c++) {
            int h = lane + 32 * c;
            if (h < ATTN_H) q2part[w][h] = a5[c];
        }
        __syncthreads();
        if (tid < ATTN_H) {
            float s = 0.f;
            #pragma unroll
            for (int i = 0; i < NWARP; i++) s += q2part[i][tid];
            q2s[tid] = s;
        }
        __syncthreads();

        // r = Wat @ q2
        for (int e0 = w; e0 < E; e0 += 32) {
            int e1 = e0 + 16;
            float s0 = 0.f, s1 = 0.f;
            const float* w0p = Wat + e0 * ATTN_H;
            const float* w1p = Wat + e1 * ATTN_H;
            #pragma unroll
            for (int c = 0; c < 5; c++) {
                int h = lane + 32 * c;
                if (h < ATTN_H) {
                    float qv = q2s[h];
                    s0 += qv * w0p[h];
                    if (e1 < E) s1 += qv * w1p[h];
                }
            }
            #pragma unroll
            for (int o = 16; o; o >>= 1) {
                s0 += __shfl_xor_sync(0xffffffffu, s0, o);
                s1 += __shfl_xor_sync(0xffffffffu, s1, o);
            }
            if (lane == 0) {
                g_r[b * E + e0] = s0;
                if (e1 < E) g_r[b * E + e1] = s1;
            }
        }
    } else {
        // out = [h1, h2] @ Wout + bias
        float o0 = 0.f, o1 = 0.f;
        for (int e = w; e < 2 * E; e += NWARP) {
            float hv = (e < E) ? h1s[e] : hs[e - E];
            const float* wr = Wout + e * NC;
            o0 += hv * wr[lane];
            if (lane < NC - 32) o1 += hv * wr[32 + lane];
        }
        opart[w][lane] = o0;
        if (lane < NC - 32) opart[w][32 + lane] = o1;
        __syncthreads();
        if (tid < NC) {
            float s = bias[tid];
            #pragma unroll
            for (int i = 0; i < NWARP; i++) s += opart[i][tid];
            out[b * NC + tid] = s;
        }
    }
}

extern "C" void kernel_launch(void* const* d_in, const int* in_sizes, int n_in,
                              void* d_out, int out_size)
{
    const int*   input_x = (const int*)  d_in[0];
    const float* emb     = (const float*)d_in[1];
    const float* query   = (const float*)d_in[2];
    const float* Wat     = (const float*)d_in[3];
    const float* Wout    = (const float*)d_in[4];
    const float* bias    = (const float*)d_in[5];
    float*       outp    = (float*)d_out;

    prep_kernel<<<296, 512>>>(emb, query);

    dim3 grid(CPB, BATCH);
    fused_stage_kernel<1><<<grid, 512>>>(input_x, Wat, Wout, bias, outp);
    fused_stage_kernel<2><<<grid, 512>>>(input_x, Wat, Wout, bias, outp);
}

// round 16
// speedup vs baseline: 1.2059x; 1.2059x over previous
#include <cuda_runtime.h>
#include <cstdint>

#define E        300
#define E4       75
#define SEQ      2048
#define BATCH    64
#define CPB      4
#define TOK_PER_CTA 512
#define TOK_PER_WARP 32
#define ATTN_H   150
#define NC       34
#define PSTRIDE  304     // h[0..300), l@300, pad
#define THREADS_P 512
#define NWARP    16

typedef unsigned long long u64;

__device__ __align__(16) float g_part[BATCH * CPB * PSTRIDE];
__device__ __align__(16) float g_h1[BATCH * E];
__device__ __align__(16) float g_r [BATCH * E];
__device__ int g_cnt[2][BATCH];   // zero-init; winner self-resets each launch

__device__ __forceinline__ u64 pk2(float lo, float hi) {
    u64 r; asm("mov.b64 %0, {%1, %2};" : "=l"(r) : "f"(lo), "f"(hi)); return r;
}
__device__ __forceinline__ void upk2(u64 v, float& lo, float& hi) {
    asm("mov.b64 {%0, %1}, %2;" : "=f"(lo), "=f"(hi) : "l"(v));
}
__device__ __forceinline__ u64 fma2(u64 a, u64 b, u64 c) {
    u64 r; asm("fma.rn.f32x2 %0, %1, %2, %3;" : "=l"(r) : "l"(a), "l"(b), "l"(c));
    return r;
}

// ---------------------------------------------------------------------------
// Fused stage kernel. grid=(CPB,BATCH), 512 thr, 2 CTAs/SM.
// Depth-2 software pipeline: 3 rolling register slots for the two main row
// quarters (A/B), 2 slots for the 11-lane tail (C). Loads for token t+2 are
// issued before computing token t => ~6-8 LDG.128 in flight per warp.
// FFMA2 packed math, no online-max (scores O(1) => raw exp safe).
//   STAGE 1: h1 -> g_h1;  r = Wat @ (h1 @ Wat) -> g_r
//   STAGE 2: h2;          out = [h1,h2] @ Wout + bias  (last CTA per batch)
// ---------------------------------------------------------------------------
template<int STAGE>
__global__ __launch_bounds__(THREADS_P, 2) void fused_stage_kernel(
    const int* __restrict__ input_x,
    const float* __restrict__ emb,
    const float* __restrict__ q_in,
    const float* __restrict__ Wat,
    const float* __restrict__ Wout,
    const float* __restrict__ bias,
    float* __restrict__ out)
{
    __shared__ float4 wacc[NWARP * 76];       // 19 KB: warp partial h
    __shared__ float  ll[NWARP];
    __shared__ float  hs[E], h1s[E];
    __shared__ float  q2part[NWARP][152];
    __shared__ float  q2s[152];
    __shared__ float  opart[NWARP][NC];
    __shared__ int    isLast;

    const int slice = blockIdx.x;
    const int b     = blockIdx.y;
    const int tid   = threadIdx.x;
    const int w     = tid >> 5;
    const int lane  = tid & 31;
    const float scale = (STAGE == 1) ? 0.05773502691896258f : 1.0f;
    const ulonglong2* __restrict__ embu = (const ulonglong2*)emb;
    ulonglong2 uz; uz.x = 0ull; uz.y = 0ull;

    // Per-batch query in packed registers, pre-scaled
    const float* qp = (STAGE == 1) ? q_in : (g_r + b * E);
    const float4* qp4 = (const float4*)qp;
    float4 t0 = qp4[lane];
    float4 t1 = qp4[lane + 32];
    float4 t2 = (lane < 11) ? qp4[lane + 64] : make_float4(0.f, 0.f, 0.f, 0.f);
    const u64 qa0 = pk2(t0.x * scale, t0.y * scale);
    const u64 qa1 = pk2(t0.z * scale, t0.w * scale);
    const u64 qb0 = pk2(t1.x * scale, t1.y * scale);
    const u64 qb1 = pk2(t1.z * scale, t1.w * scale);
    const u64 qc0 = pk2(t2.x * scale, t2.y * scale);
    const u64 qc1 = pk2(t2.z * scale, t2.w * scale);

    // This warp's 32 token indices
    const int myidx = input_x[b * SEQ + slice * TOK_PER_CTA + w * TOK_PER_WARP + lane];

    float l = 0.f;
    u64 Ax = 0ull, Ay = 0ull, Bx = 0ull, By = 0ull, Cx = 0ull, Cy = 0ull;

    // Rolling pipeline slots
    ulonglong2 SA[3], SB[3], SC[2];
    SC[0] = uz; SC[1] = uz;
    {
        int r0 = __shfl_sync(0xffffffffu, myidx, 0);
        const ulonglong2* p0 = embu + (long long)r0 * E4;
        SA[0] = p0[lane]; SB[0] = p0[lane + 32];
        if (lane < 11) SC[0] = p0[lane + 64];
        int r1 = __shfl_sync(0xffffffffu, myidx, 1);
        const ulonglong2* p1 = embu + (long long)r1 * E4;
        SA[1] = p1[lane]; SB[1] = p1[lane + 32];
        if (lane < 11) SC[1] = p1[lane + 64];
    }

    #pragma unroll
    for (int t = 0; t < TOK_PER_WARP; t++) {
        ulonglong2 ca = SA[t % 3], cb = SB[t % 3], cc = SC[t % 2];

        // Issue loads for t+2 (full-mask broadcast of the row index ONCE)
        if (t + 2 < TOK_PER_WARP) {
            int rn = __shfl_sync(0xffffffffu, myidx, t + 2);
            const ulonglong2* np = embu + (long long)rn * E4;
            SA[(t + 2) % 3] = np[lane];
            SB[(t + 2) % 3] = np[lane + 32];
            if (lane < 11) SC[t % 2] = np[lane + 64];  // slot just consumed
        }

        // Packed dot: 6 FFMA2
        u64 d = fma2(ca.x, qa0, 0ull);
        d = fma2(ca.y, qa1, d);
        d = fma2(cb.x, qb0, d);
        d = fma2(cb.y, qb1, d);
        d = fma2(cc.x, qc0, d);
        d = fma2(cc.y, qc1, d);
        float lo, hi;
        upk2(d, lo, hi);
        float s = lo + hi;
        #pragma unroll
        for (int o = 16; o; o >>= 1) s += __shfl_xor_sync(0xffffffffu, s, o);

        float wt = __expf(s);       // scale pre-folded into q
        l += wt;
        u64 ww = pk2(wt, wt);
        Ax = fma2(ca.x, ww, Ax);  Ay = fma2(ca.y, ww, Ay);
        Bx = fma2(cb.x, ww, Bx);  By = fma2(cb.y, ww, By);
        Cx = fma2(cc.x, ww, Cx);  Cy = fma2(cc.y, ww, Cy);
    }

    // ---- CTA merge of 16 warp partials (pure sums)
    if (lane == 0) ll[w] = l;
    ulonglong2* waccu = (ulonglong2*)wacc;
    { ulonglong2 v; v.x = Ax; v.y = Ay; waccu[w * 76 + lane]      = v; }
    { ulonglong2 v; v.x = Bx; v.y = By; waccu[w * 76 + lane + 32] = v; }
    if (lane < 11) { ulonglong2 v; v.x = Cx; v.y = Cy; waccu[w * 76 + lane + 64] = v; }
    __syncthreads();

    float* p = g_part + (b * CPB + slice) * PSTRIDE;
    if (tid < E4) {
        float4 ssum = make_float4(0.f, 0.f, 0.f, 0.f);
        #pragma unroll
        for (int i = 0; i < NWARP; i++) {
            float4 v = wacc[i * 76 + tid];
            ssum.x += v.x; ssum.y += v.y; ssum.z += v.z; ssum.w += v.w;
        }
        ((float4*)p)[tid] = ssum;
    }
    if (tid == 0) {
        float Ls = 0.f;
        #pragma unroll
        for (int i = 0; i < NWARP; i++) Ls += ll[i];
        p[300] = Ls;
    }

    // ---- Last CTA per batch merges CPB partials + epilogue
    __syncthreads();
    if (tid == 0) {
        __threadfence();
        int old = atomicAdd(&g_cnt[STAGE - 1][b], 1);
        isLast = (old == CPB - 1);
        if (isLast) g_cnt[STAGE - 1][b] = 0;   // self-reset for graph replay
    }
    __syncthreads();
    if (!isLast) return;
    __threadfence();

    const float* pb = g_part + b * CPB * PSTRIDE;
    if (tid == 0) {
        float Lg = 0.f;
        #pragma unroll
        for (int i = 0; i < CPB; i++) Lg += pb[i * PSTRIDE + 300];
        q2s[151] = 1.f / Lg;     // stash invL in shared
    }
    __syncthreads();
    const float invL = q2s[151];

    if (tid < E) {
        float s = 0.f;
        #pragma unroll
        for (int i = 0; i < CPB; i++) s += pb[i * PSTRIDE + tid];
        s *= invL;
        hs[tid] = s;
        if (STAGE == 1) g_h1[b * E + tid] = s;
        else            h1s[tid] = g_h1[b * E + tid];
    }
    __syncthreads();

    if (STAGE == 1) {
        // q2 = h1 @ Wat — 16-warp split over e, 5 chains/lane
        float a5[5] = {0.f, 0.f, 0.f, 0.f, 0.f};
        for (int e = w; e < E; e += NWARP) {
            float hv = hs[e];
            const float* wr = Wat + e * ATTN_H;
            #pragma unroll
            for (int c = 0; c < 5; c++) {
                int h = lane + 32 * c;
                if (h < ATTN_H) a5[c] += hv * wr[h];
            }
        }
        #pragma unroll
        for (int c = 0; c < 5; c++) {
            int h = lane + 32 * c;
            if (h < ATTN_H) q2part[w][h] = a5[c];
        }
        __syncthreads();
        if (tid < ATTN_H) {
            float s = 0.f;
            #pragma unroll
            for (int i = 0; i < NWARP; i++) s += q2part[i][tid];
            q2s[tid] = s;
        }
        __syncthreads();

        // r = Wat @ q2 — warp per (e0, e0+16)
        for (int e0 = w; e0 < E; e0 += 32) {
            int e1 = e0 + 16;
            float s0 = 0.f, s1 = 0.f;
            const float* w0p = Wat + e0 * ATTN_H;
            const float* w1p = Wat + e1 * ATTN_H;
            #pragma unroll
            for (int c = 0; c < 5; c++) {
                int h = lane + 32 * c;
                if (h < ATTN_H) {
                    float qv = q2s[h];
                    s0 += qv * w0p[h];
                    if (e1 < E) s1 += qv * w1p[h];
                }
            }
            #pragma unroll
            for (int o = 16; o; o >>= 1) {
                s0 += __shfl_xor_sync(0xffffffffu, s0, o);
                s1 += __shfl_xor_sync(0xffffffffu, s1, o);
            }
            if (lane == 0) {
                g_r[b * E + e0] = s0;
                if (e1 < E) g_r[b * E + e1] = s1;
            }
        }
    } else {
        // out = [h1, h2] @ Wout + bias — 16-warp split over 600 rows
        float o0 = 0.f, o1 = 0.f;
        for (int e = w; e < 2 * E; e += NWARP) {
            float hv = (e < E) ? h1s[e] : hs[e - E];
            const float* wr = Wout + e * NC;
            o0 += hv * wr[lane];
            if (lane < NC - 32) o1 += hv * wr[32 + lane];
        }
        opart[w][lane] = o0;
        if (lane < NC - 32) opart[w][32 + lane] = o1;
        __syncthreads();
        if (tid < NC) {
            float s = bias[tid];
            #pragma unroll
            for (int i = 0; i < NWARP; i++) s += opart[i][tid];
            out[b * NC + tid] = s;
        }
    }
}

extern "C" void kernel_launch(void* const* d_in, const int* in_sizes, int n_in,
                              void* d_out, int out_size)
{
    const int*   input_x = (const int*)  d_in[0];
    const float* emb     = (const float*)d_in[1];
    const float* query   = (const float*)d_in[2];
    const float* Wat     = (const float*)d_in[3];
    const float* Wout    = (const float*)d_in[4];
    const float* bias    = (const float*)d_in[5];
    float*       outp    = (float*)d_out;

    dim3 grid(CPB, BATCH);
    fused_stage_kernel<1><<<grid, THREADS_P>>>(
        input_x, emb, query, Wat, Wout, bias, outp);
    fused_stage_kernel<2><<<grid, THREADS_P>>>(
        input_x, emb, query, Wat, Wout, bias, outp);
}

// round 17
// speedup vs baseline: 1.2567x; 1.0421x over previous
#include <cuda_runtime.h>
#include <cstdint>

#define E        300
#define E4       75
#define SEQ      2048
#define BATCH    64
#define CPB      4
#define TOK_PER_CTA 512
#define TOK_PER_WARP 32
#define ATTN_H   150
#define NC       34
#define PSTRIDE  304     // h[0..300), l@300, pad
#define THREADS_P 512
#define NWARP    16

typedef unsigned long long u64;

__device__ __align__(16) float g_part[BATCH * CPB * PSTRIDE];
__device__ __align__(16) float g_h1[BATCH * E];
__device__ __align__(16) float g_r [BATCH * E];
__device__ int g_cnt[2][BATCH];   // zero-init; winners self-reset
__device__ int g_ready[BATCH];    // zero-init; phase-2 winner resets

__device__ __forceinline__ u64 pk2(float lo, float hi) {
    u64 r; asm("mov.b64 %0, {%1, %2};" : "=l"(r) : "f"(lo), "f"(hi)); return r;
}
__device__ __forceinline__ void upk2(u64 v, float& lo, float& hi) {
    asm("mov.b64 {%0, %1}, %2;" : "=f"(lo), "=f"(hi) : "l"(v));
}
__device__ __forceinline__ u64 fma2(u64 a, u64 b, u64 c) {
    u64 r; asm("fma.rn.f32x2 %0, %1, %2, %3;" : "=l"(r) : "l"(a), "l"(b), "l"(c));
    return r;
}

// R12 mainloop: 32-token gather-softmax pass, depth-1 prefetch, FFMA2.
// Query passed pre-scaled & packed. Accumulates l and 6 packed f32x2 sums.
__device__ __forceinline__ void gather_pass(
    const ulonglong2* __restrict__ embu, int myidx, int lane,
    u64 qa0, u64 qa1, u64 qb0, u64 qb1, u64 qc0, u64 qc1,
    float& l, u64& Ax, u64& Ay, u64& Bx, u64& By, u64& Cx, u64& Cy)
{
    ulonglong2 uz; uz.x = 0ull; uz.y = 0ull;
    int row0 = __shfl_sync(0xffffffffu, myidx, 0);
    const ulonglong2* sp = embu + (long long)row0 * E4;
    ulonglong2 na = sp[lane];
    ulonglong2 nb = sp[lane + 32];
    ulonglong2 nc = (lane < 11) ? sp[lane + 64] : uz;

    #pragma unroll 4
    for (int t = 0; t < TOK_PER_WARP; t++) {
        ulonglong2 ca = na, cb = nb, cc = nc;
        if (t + 1 < TOK_PER_WARP) {
            int rn = __shfl_sync(0xffffffffu, myidx, t + 1);
            const ulonglong2* np = embu + (long long)rn * E4;
            na = np[lane];
            nb = np[lane + 32];
            if (lane < 11) nc = np[lane + 64];
        }
        u64 d = fma2(ca.x, qa0, 0ull);
        d = fma2(ca.y, qa1, d);
        d = fma2(cb.x, qb0, d);
        d = fma2(cb.y, qb1, d);
        d = fma2(cc.x, qc0, d);
        d = fma2(cc.y, qc1, d);
        float lo, hi;
        upk2(d, lo, hi);
        float s = lo + hi;
        #pragma unroll
        for (int o = 16; o; o >>= 1) s += __shfl_xor_sync(0xffffffffu, s, o);

        float wt = __expf(s);
        l += wt;
        u64 ww = pk2(wt, wt);
        Ax = fma2(ca.x, ww, Ax);  Ay = fma2(ca.y, ww, Ay);
        Bx = fma2(cb.x, ww, Bx);  By = fma2(cb.y, ww, By);
        Cx = fma2(cc.x, ww, Cx);  Cy = fma2(cc.y, ww, Cy);
    }
}

// ---------------------------------------------------------------------------
// Single fused kernel: both stages, one launch. grid=(CPB,BATCH), 512 thr,
// 2 CTAs/SM => all 256 CTAs co-resident => inter-phase spin is safe.
// Phase 1: gather with q -> h1, r (last CTA per batch), set ready flag.
// Phase 2: re-gather SAME rows (L2-hot) with r -> h2 -> output GEMM.
// ---------------------------------------------------------------------------
__global__ __launch_bounds__(THREADS_P, 2) void fused_all_kernel(
    const int* __restrict__ input_x,
    const float* __restrict__ emb,
    const float* __restrict__ q_in,
    const float* __restrict__ Wat,
    const float* __restrict__ Wout,
    const float* __restrict__ bias,
    float* __restrict__ out)
{
    __shared__ float4 wacc[NWARP * 76];
    __shared__ float  ll[NWARP];
    __shared__ float  hs[E], h1s[E];
    __shared__ float  q2part[NWARP][152];
    __shared__ float  q2s[152];
    __shared__ float  opart[NWARP][NC];
    __shared__ int    isLast;

    const int slice = blockIdx.x;
    const int b     = blockIdx.y;
    const int tid   = threadIdx.x;
    const int w     = tid >> 5;
    const int lane  = tid & 31;
    const ulonglong2* __restrict__ embu = (const ulonglong2*)emb;
    const float4 fz = make_float4(0.f, 0.f, 0.f, 0.f);

    const int myidx = input_x[b * SEQ + slice * TOK_PER_CTA + w * TOK_PER_WARP + lane];
    float* p = g_part + (b * CPB + slice) * PSTRIDE;

    for (int phase = 0; phase < 2; phase++) {
        // ---- Build packed, pre-scaled query
        const float scale = (phase == 0) ? 0.05773502691896258f : 1.0f;
        const float* qp   = (phase == 0) ? q_in : (g_r + b * E);
        const float4* qp4 = (const float4*)qp;
        float4 t0 = qp4[lane];
        float4 t1 = qp4[lane + 32];
        float4 t2 = (lane < 11) ? qp4[lane + 64] : fz;
        u64 qa0 = pk2(t0.x * scale, t0.y * scale);
        u64 qa1 = pk2(t0.z * scale, t0.w * scale);
        u64 qb0 = pk2(t1.x * scale, t1.y * scale);
        u64 qb1 = pk2(t1.z * scale, t1.w * scale);
        u64 qc0 = pk2(t2.x * scale, t2.y * scale);
        u64 qc1 = pk2(t2.z * scale, t2.w * scale);

        float l = 0.f;
        u64 Ax = 0ull, Ay = 0ull, Bx = 0ull, By = 0ull, Cx = 0ull, Cy = 0ull;
        gather_pass(embu, myidx, lane, qa0, qa1, qb0, qb1, qc0, qc1,
                    l, Ax, Ay, Bx, By, Cx, Cy);

        // ---- CTA merge of 16 warp partials
        if (lane == 0) ll[w] = l;
        ulonglong2* waccu = (ulonglong2*)wacc;
        { ulonglong2 v; v.x = Ax; v.y = Ay; waccu[w * 76 + lane]      = v; }
        { ulonglong2 v; v.x = Bx; v.y = By; waccu[w * 76 + lane + 32] = v; }
        if (lane < 11) { ulonglong2 v; v.x = Cx; v.y = Cy; waccu[w * 76 + lane + 64] = v; }
        __syncthreads();

        if (tid < E4) {
            float4 ssum = fz;
            #pragma unroll
            for (int i = 0; i < NWARP; i++) {
                float4 v = wacc[i * 76 + tid];
                ssum.x += v.x; ssum.y += v.y; ssum.z += v.z; ssum.w += v.w;
            }
            ((float4*)p)[tid] = ssum;
        }
        if (tid == 0) {
            float Ls = 0.f;
            #pragma unroll
            for (int i = 0; i < NWARP; i++) Ls += ll[i];
            p[300] = Ls;
        }
        __syncthreads();

        // ---- Last CTA per batch merges + epilogue
        if (tid == 0) {
            __threadfence();
            int old = atomicAdd(&g_cnt[phase][b], 1);
            isLast = (old == CPB - 1);
            if (isLast) g_cnt[phase][b] = 0;   // self-reset for replay
        }
        __syncthreads();

        if (isLast) {
            __threadfence();
            const float* pb = g_part + b * CPB * PSTRIDE;
            if (tid == 0) {
                float Lg = 0.f;
                #pragma unroll
                for (int i = 0; i < CPB; i++) Lg += pb[i * PSTRIDE + 300];
                q2s[151] = 1.f / Lg;
            }
            __syncthreads();
            const float invL = q2s[151];

            if (tid < E) {
                float s = 0.f;
                #pragma unroll
                for (int i = 0; i < CPB; i++) s += pb[i * PSTRIDE + tid];
                s *= invL;
                hs[tid] = s;
                if (phase == 0) g_h1[b * E + tid] = s;
                else            h1s[tid] = g_h1[b * E + tid];
            }
            __syncthreads();

            if (phase == 0) {
                // q2 = h1 @ Wat
                float a5[5] = {0.f, 0.f, 0.f, 0.f, 0.f};
                for (int e = w; e < E; e += NWARP) {
                    float hv = hs[e];
                    const float* wr = Wat + e * ATTN_H;
                    #pragma unroll
                    for (int c = 0; c < 5; c++) {
                        int h = lane + 32 * c;
                        if (h < ATTN_H) a5[c] += hv * wr[h];
                    }
                }
                #pragma unroll
                for (int c = 0; c < 5; c++) {
                    int h = lane + 32 * c;
                    if (h < ATTN_H) q2part[w][h] = a5[c];
                }
                __syncthreads();
                if (tid < ATTN_H) {
                    float s = 0.f;
                    #pragma unroll
                    for (int i = 0; i < NWARP; i++) s += q2part[i][tid];
                    q2s[tid] = s;
                }
                __syncthreads();

                // r = Wat @ q2
                for (int e0 = w; e0 < E; e0 += 32) {
                    int e1 = e0 + 16;
                    float s0 = 0.f, s1 = 0.f;
                    const float* w0p = Wat + e0 * ATTN_H;
                    const float* w1p = Wat + e1 * ATTN_H;
                    #pragma unroll
                    for (int c = 0; c < 5; c++) {
                        int h = lane + 32 * c;
                        if (h < ATTN_H) {
                            float qv = q2s[h];
                            s0 += qv * w0p[h];
                            if (e1 < E) s1 += qv * w1p[h];
                        }
                    }
                    #pragma unroll
                    for (int o = 16; o; o >>= 1) {
                        s0 += __shfl_xor_sync(0xffffffffu, s0, o);
                        s1 += __shfl_xor_sync(0xffffffffu, s1, o);
                    }
                    if (lane == 0) {
                        g_r[b * E + e0] = s0;
                        if (e1 < E) g_r[b * E + e1] = s1;
                    }
                }
                // publish r
                __syncthreads();
                if (tid == 0) {
                    __threadfence();
                    atomicExch(&g_ready[b], 1);
                }
            } else {
                // out = [h1, h2] @ Wout + bias
                float o0 = 0.f, o1 = 0.f;
                for (int e = w; e < 2 * E; e += NWARP) {
                    float hv = (e < E) ? h1s[e] : hs[e - E];
                    const float* wr = Wout + e * NC;
                    o0 += hv * wr[lane];
                    if (lane < NC - 32) o1 += hv * wr[32 + lane];
                }
                opart[w][lane] = o0;
                if (lane < NC - 32) opart[w][32 + lane] = o1;
                __syncthreads();
                if (tid < NC) {
                    float s = bias[tid];
                    #pragma unroll
                    for (int i = 0; i < NWARP; i++) s += opart[i][tid];
                    out[b * NC + tid] = s;
                }
                if (tid == 0) {
                    __threadfence();
                    g_ready[b] = 0;            // reset for next graph replay
                }
            }
        }

        // ---- Inter-phase barrier: wait for this batch's r
        if (phase == 0) {
            if (tid == 0) {
                while (atomicAdd(&g_ready[b], 0) == 0) { __nanosleep(64); }
            }
            __syncthreads();
            __threadfence();
        }
    }
}

extern "C" void kernel_launch(void* const* d_in, const int* in_sizes, int n_in,
                              void* d_out, int out_size)
{
    const int*   input_x = (const int*)  d_in[0];
    const float* emb     = (const float*)d_in[1];
    const float* query   = (const float*)d_in[2];
    const float* Wat     = (const float*)d_in[3];
    const float* Wout    = (const float*)d_in[4];
    const float* bias    = (const float*)d_in[5];
    float*       outp    = (float*)d_out;

    dim3 grid(CPB, BATCH);
    fused_all_kernel<<<grid, THREADS_P>>>(
        input_x, emb, query, Wat, Wout, bias, outp);
}